// round 6
// baseline (speedup 1.0000x reference)
#include <cuda_runtime.h>

#define T_DIM 1024
#define B_DIM 128
#define H_DIM 256
#define CHUNK 64
#define NCHUNK 16                 // 16 * 64 = 1024 steps
#define NCTA 148
#define NWORK (NCTA - 1)          // 147 worker CTAs
#define BLK 512
#define NWARPW (NWORK * 16)       // worker warps (xdot)
#define NTHW (NWORK * BLK)        // worker threads (bcast)

// Scratch (__device__ globals; allocation-free rule).
__device__ __align__(16) float g_xdot[(T_DIM + 8) * B_DIM * 4]; // [t][b][4], padded
__device__ __align__(16) float g_h[T_DIM * B_DIM];              // [t][b]
__device__ __align__(16) float g_c[B_DIM];
__device__ int g_xdone[NCHUNK];
__device__ int g_rdone;

// ---- fast math helpers -----------------------------------------------------
__device__ __forceinline__ float sin_ap(float x) {
    float r; asm("sin.approx.f32 %0, %1;" : "=f"(r) : "f"(x)); return r;
}
__device__ __forceinline__ float rcp_ap(float x) {
    float r; asm("rcp.approx.f32 %0, %1;" : "=f"(r) : "f"(x)); return r;
}
// tanh continued fraction depth 6, |x|<=2.2 (err ~3e-6; |c|<=2.07 provably). One rcp.
__device__ __forceinline__ float tanh_p6(float x) {
    float u  = x * x;
    float u2 = u * u;
    float n  = fmaf(fmaf(21.0f, u, 1260.0f), u, 10395.0f);
    float d  = fmaf(u2, u + 210.0f, fmaf(4725.0f, u, 10395.0f));
    return x * n * rcp_ap(d);
}

__device__ __forceinline__ void waitGe(const int* p, int v) {
    while (*(volatile const int*)p < v) __nanosleep(64);
}

// ---- zero the cross-CTA flags ----------------------------------------------
__global__ void k_zero() {
    int i = threadIdx.x;
    if (i < NCHUNK) g_xdone[i] = 0;
    if (i == NCHUNK) g_rdone = 0;
}

// ---- fused persistent kernel ----------------------------------------------
__global__ __launch_bounds__(BLK, 1) void k_fused(const float* __restrict__ in,
                                                  const float* __restrict__ Wt,
                                                  const float* __restrict__ bias,
                                                  float* __restrict__ out) {
    const int cta = blockIdx.x;
    const int tid = threadIdx.x;
    const int lane = tid & 31;
    const unsigned FULL = 0xffffffffu;

    if (cta == 0) {
        // ====== recurrence CTA: 4 lanes per chain, 128 quads, 16 warps ======
        const int r = tid & 3;          // gate role: 0=f 1=i 2=g 3=o
        const int b = tid >> 2;         // batch chain 0..127

        // per-role gate constants: sigmoid(x) = 0.5 + 0.5*tanh(x/2); tanh: k=m=1,C=0
        const float kr = (r == 2) ? 1.0f : 0.5f;
        const float mr = (r == 2) ? 1.0f : 0.5f;
        const float Cr = (r == 2) ? 0.0f : 0.5f;

        // whsum[r] = sum_h W[r, 256+h]; 8 same-role lanes split the 256 terms
        float wv;
        {
            const int qw = (lane >> 2);                 // 0..7
            const float* wr = Wt + r * 512 + 256;
            float s = 0.f;
#pragma unroll
            for (int k = 0; k < 32; k++) s += wr[qw + k * 8];
            s += __shfl_xor_sync(FULL, s, 4);
            s += __shfl_xor_sync(FULL, s, 8);
            s += __shfl_xor_sync(FULL, s, 16);
            wv = s;                                     // whsum for this lane's role
        }

        if (tid == 0) waitGe(&g_xdone[0], NWORK);
        __syncthreads();

        // layout trick: g_xdot[t*512 + tid] is exactly this lane's (b, r) slot
        float lin = g_xdot[tid];
        float buf[4];
#pragma unroll
        for (int k = 0; k < 4; k++) buf[k] = g_xdot[(k + 1) * 512 + tid];

        float c = 0.f;
        for (int ch = 0; ch < NCHUNK; ch++) {
            int c2 = (ch + 1 < NCHUNK) ? ch + 1 : NCHUNK - 1;
            if (tid == 0) { waitGe(&g_xdone[ch], NWORK); waitGe(&g_xdone[c2], NWORK); }
            __syncthreads();

            const int t0 = ch * CHUNK;
#pragma unroll 4
            for (int t = t0; t < t0 + CHUNK; t++) {
                float nxt = buf[t & 3];
                buf[t & 3] = g_xdot[(t + 5) * 512 + tid];   // prefetch, off-chain

                // unified per-role gate: C + m * tanh_cf4(k * sin(lin))
                float s  = sin_ap(lin);
                float x  = kr * s;
                float u  = x * x;
                float n  = x * fmaf(10.0f, u, 105.0f);
                float d  = fmaf(u, u + 45.0f, 105.0f);
                float v  = fmaf(n * rcp_ap(d), mr, Cr);

                float f  = __shfl_sync(FULL, v, 0, 4);
                float i_ = __shfl_sync(FULL, v, 1, 4);
                float gg = __shfl_sync(FULL, v, 2, 4);
                float o  = __shfl_sync(FULL, v, 3, 4);

                c = fmaf(f, c, i_ * gg);
                float tc = tanh_p6(c);       // redundant across quad lanes
                float h  = o * tc;
                lin = fmaf(wv, h, nxt);
                if (r == 0) g_h[t * B_DIM + b] = h;   // 8 lanes/warp, coalesced
            }
            if (ch == NCHUNK - 1 && r == 0) g_c[b] = c;
            __threadfence();
            __syncthreads();
            if (tid == 0) *(volatile int*)&g_rdone = (ch + 1) * CHUNK;
        }
        return;
    }

    // ================= worker CTAs: xdot then bcast =================
    __shared__ float4 sW[4][64];
    for (int i = tid; i < 4 * 64; i += BLK) {
        int g = i >> 6, cc = i & 63;
        sW[g][cc] = reinterpret_cast<const float4*>(Wt)[g * 128 + cc];
    }
    __syncthreads();

    const int warp = tid >> 5;
    const int wg = (cta - 1) * 16 + warp;
    const float bv = (lane < 4) ? bias[lane] : 0.f;
    const float4* in4 = reinterpret_cast<const float4*>(in);

    for (int ch = 0; ch < NCHUNK; ch++) {
        const int pe = (ch + 1) * CHUNK * B_DIM;
        for (int p = ch * CHUNK * B_DIM + wg; p < pe; p += NWARPW) {
            const float4* src = in4 + (long)p * 64;
            float4 a0 = src[lane];
            float4 a1 = src[lane + 32];
            float s[4];
#pragma unroll
            for (int g = 0; g < 4; g++) {
                float4 w = sW[g][lane];
                float t = a0.x * w.x + a0.y * w.y + a0.z * w.z + a0.w * w.w;
                w = sW[g][lane + 32];
                t += a1.x * w.x + a1.y * w.y + a1.z * w.z + a1.w * w.w;
                s[g] = t;
            }
            // packed 6-shuffle reduction of 4 sums
            bool b0 = lane & 1;
            float t01 = b0 ? s[0] : s[1];
            float k01 = b0 ? s[1] : s[0];
            k01 += __shfl_xor_sync(FULL, t01, 1);
            float t23 = b0 ? s[2] : s[3];
            float k23 = b0 ? s[3] : s[2];
            k23 += __shfl_xor_sync(FULL, t23, 1);
            bool b1 = lane & 2;
            float tv = b1 ? k01 : k23;
            float kv = b1 ? k23 : k01;
            kv += __shfl_xor_sync(FULL, tv, 2);
            kv += __shfl_xor_sync(FULL, kv, 4);
            kv += __shfl_xor_sync(FULL, kv, 8);
            kv += __shfl_xor_sync(FULL, kv, 16);
            if (lane < 4) g_xdot[p * 4 + lane] = kv + bv;
        }
        __threadfence();
        __syncthreads();
        if (tid == 0) atomicAdd(&g_xdone[ch], 1);
    }

    // ---- bcast phase: trail the recurrence ----
    float4* out4 = reinterpret_cast<float4*>(out);
    const int widx = (cta - 1) * BLK + tid;
    const long S4 = (long)T_DIM * B_DIM * H_DIM / 4;   // 8388608
    for (int ch = 0; ch < NCHUNK; ch++) {
        if (tid == 0) waitGe(&g_rdone, (ch + 1) * CHUNK);
        __syncthreads();
        const long base = (long)ch * CHUNK * (B_DIM * H_DIM / 4);
        const long end  = base + (long)CHUNK * (B_DIM * H_DIM / 4);
        for (long i = base + widx; i < end; i += NTHW) {
            int t = (int)(i >> 13);            // 8192 float4 per t
            int b = (int)(i >> 6) & 127;
            float v = g_h[t * B_DIM + b];      // warp-uniform load
            out4[i] = make_float4(v, v, v, v);
        }
    }
    // tails: hx (== h at t=1023) and cx
    for (long i = S4 + widx; i < S4 + 16384; i += NTHW) {
        int rr = (int)(i - S4);
        float v;
        if (rr < 8192) v = g_h[(T_DIM - 1) * B_DIM + (rr >> 6)];
        else           v = g_c[(rr - 8192) >> 6];
        out4[i] = make_float4(v, v, v, v);
    }
}

extern "C" void kernel_launch(void* const* d_in, const int* in_sizes, int n_in,
                              void* d_out, int out_size) {
    const float* in   = (const float*)d_in[0];   // [T,B,D]
    const float* Wt   = (const float*)d_in[1];   // [4, D+H]
    const float* bias = (const float*)d_in[2];   // [4]
    // d_in[3] (qw) mathematically has no effect on the output.
    float* out = (float*)d_out;

    k_zero<<<1, 32>>>();
    k_fused<<<NCTA, BLK>>>(in, Wt, bias, out);
}

// round 7
// speedup vs baseline: 1.0760x; 1.0760x over previous
#include <cuda_runtime.h>

#define T_DIM 1024
#define B_DIM 128
#define H_DIM 256
#define CHUNK 64
#define NCHUNK 16                 // 16 * 64 = 1024 steps
#define NCTA 148
#define NWORK (NCTA - 1)          // 147 worker CTAs
#define NWARPW (NWORK * 8)        // worker warps (xdot)
#define NTHW (NWORK * 256)        // worker threads (bcast)

// Scratch (__device__ globals; allocation-free rule).
__device__ __align__(16) float g_xdot[(T_DIM + 8) * B_DIM * 4]; // [t][b][4], padded
__device__ __align__(16) float g_h[T_DIM * B_DIM];              // [t][b]
__device__ __align__(16) float g_c[B_DIM];
__device__ int g_xdone[NCHUNK];
__device__ int g_rdone;

typedef unsigned long long ull;

// ---- fast math helpers -----------------------------------------------------
__device__ __forceinline__ float sin_ap(float x) {
    float r; asm("sin.approx.f32 %0, %1;" : "=f"(r) : "f"(x)); return r;
}
__device__ __forceinline__ float rcp_ap(float x) {
    float r; asm("rcp.approx.f32 %0, %1;" : "=f"(r) : "f"(x)); return r;
}
// packed f32x2 ops (Blackwell FFMA2 path — PTX only)
__device__ __forceinline__ ull pk2(float lo, float hi) {
    ull r; asm("mov.b64 %0, {%1, %2};" : "=l"(r) : "f"(lo), "f"(hi)); return r;
}
__device__ __forceinline__ void up2(ull v, float& lo, float& hi) {
    asm("mov.b64 {%0, %1}, %2;" : "=f"(lo), "=f"(hi) : "l"(v));
}
__device__ __forceinline__ ull fma2(ull a, ull b, ull c) {
    ull r; asm("fma.rn.f32x2 %0, %1, %2, %3;" : "=l"(r) : "l"(a), "l"(b), "l"(c)); return r;
}
__device__ __forceinline__ ull mul2(ull a, ull b) {
    ull r; asm("mul.rn.f32x2 %0, %1, %2;" : "=l"(r) : "l"(a), "l"(b)); return r;
}

// sigmoid(s) coeffs, |s|<=1, deg-4 in u=s^2, abs err ~2e-6 (validated R4/R6).
#define SA0 0.25f
#define SA1 (-2.0833333e-2f)
#define SA2 2.0833333e-3f
#define SA3 (-2.1081349e-4f)
#define SA4 2.1356790e-5f

// tanh continued fraction depth 6, |x|<=2.2 (err ~3e-6; |c|<=2.07 provably). One rcp.
__device__ __forceinline__ float tanh_p6(float x) {
    float u  = x * x;
    float u2 = u * u;
    float n  = fmaf(fmaf(21.0f, u, 1260.0f), u, 10395.0f);
    float d  = fmaf(u2, u + 210.0f, fmaf(4725.0f, u, 10395.0f));
    return x * n * rcp_ap(d);
}

__device__ __forceinline__ void waitGe(const int* p, int v) {
    while (*(volatile const int*)p < v) __nanosleep(64);
}

// ---- zero the cross-CTA flags ----------------------------------------------
__global__ void k_zero() {
    int i = threadIdx.x;
    if (i < NCHUNK) g_xdone[i] = 0;
    if (i == NCHUNK) g_rdone = 0;
}

// ---- fused persistent kernel ----------------------------------------------
__global__ __launch_bounds__(256, 1) void k_fused(const float* __restrict__ in,
                                                  const float* __restrict__ Wt,
                                                  const float* __restrict__ bias,
                                                  float* __restrict__ out) {
    const int cta = blockIdx.x;
    const int tid = threadIdx.x;
    const int lane = tid & 31;
    const unsigned FULL = 0xffffffffu;

    if (cta == 0) {
        // ========== recurrence CTA: 4 warps, 1 chain per thread ==========
        if (tid >= 128) return;
        float wh[4];
#pragma unroll
        for (int g = 0; g < 4; g++) {
            const float* wr = Wt + g * 512 + 256;
            float s = 0.f;
#pragma unroll
            for (int k = 0; k < 8; k++) s += wr[lane + k * 32];
#pragma unroll
            for (int o = 16; o; o >>= 1) s += __shfl_xor_sync(FULL, s, o);
            wh[g] = s;
        }
        const float w0 = wh[0], w1 = wh[1], w2 = wh[2], w3 = wh[3];

        const int b = tid;
        const float4* xd4 = reinterpret_cast<const float4*>(g_xdot);

        // hoisted packed constants for the (f,i) x2 sigmoid
        const ull cA0 = pk2(SA0, SA0), cA1 = pk2(SA1, SA1), cA2 = pk2(SA2, SA2),
                  cA3 = pk2(SA3, SA3), cA4 = pk2(SA4, SA4), cH = pk2(0.5f, 0.5f);

        if (tid == 0) waitGe(&g_xdone[0], NWORK);
        __syncthreads();

        float4 x0 = xd4[b];
        float lf = x0.x, li = x0.y, lg = x0.z, lo = x0.w;
        float4 buf[4];
#pragma unroll
        for (int k = 0; k < 4; k++) buf[k] = xd4[(k + 1) * B_DIM + b];

        float c = 0.f;
        for (int ch = 0; ch < NCHUNK; ch++) {
            int c2 = (ch + 1 < NCHUNK) ? ch + 1 : NCHUNK - 1;
            if (tid == 0) { waitGe(&g_xdone[ch], NWORK); waitGe(&g_xdone[c2], NWORK); }
            __syncthreads();

            const int t0 = ch * CHUNK;
#pragma unroll 4
            for (int t = t0; t < t0 + CHUNK; t++) {
                float4 nxt = buf[t & 3];
                buf[t & 3] = xd4[(t + 5) * B_DIM + b];   // prefetch, off-chain

                float sf = sin_ap(lf);
                float si = sin_ap(li);
                float sg = sin_ap(lg);
                float so = sin_ap(lo);

                // (f,i): packed x2 sigmoid (deg-4 in u)
                ull sfi = pk2(sf, si);
                ull u   = mul2(sfi, sfi);
                ull uu  = mul2(u, u);
                ull b0p = fma2(cA1, u, cA0);
                ull b1p = fma2(cA3, u, cA2);
                ull pp  = fma2(fma2(cA4, uu, b1p), uu, b0p);
                ull vfi = fma2(sfi, pp, cH);
                float f, i_; up2(vfi, f, i_);

                // g: scalar tanh CF depth-4
                float ug = sg * sg;
                float ng = sg * fmaf(10.0f, ug, 105.0f);
                float dg = fmaf(ug, ug + 45.0f, 105.0f);
                float gg = ng * rcp_ap(dg);

                // o: scalar sigmoid deg-4
                float uo  = so * so;
                float uo2 = uo * uo;
                float ob0 = fmaf(SA1, uo, SA0);
                float ob1 = fmaf(SA3, uo, SA2);
                float op  = fmaf(fmaf(SA4, uo2, ob1), uo2, ob0);
                float o   = fmaf(so, op, 0.5f);

                c = fmaf(f, c, i_ * gg);
                float tc = tanh_p6(c);
                float h  = o * tc;
                lf = fmaf(w0, h, nxt.x);
                li = fmaf(w1, h, nxt.y);
                lg = fmaf(w2, h, nxt.z);
                lo = fmaf(w3, h, nxt.w);
                g_h[t * B_DIM + b] = h;                 // coalesced STG.32, off-chain
            }
            if (ch == NCHUNK - 1) g_c[b] = c;
            __threadfence();
            __syncthreads();
            if (tid == 0) *(volatile int*)&g_rdone = (ch + 1) * CHUNK;
        }
        return;
    }

    // ================= worker CTAs: xdot then bcast =================
    __shared__ float4 sW[4][64];
    for (int i = tid; i < 4 * 64; i += 256) {
        int g = i >> 6, cc = i & 63;
        sW[g][cc] = reinterpret_cast<const float4*>(Wt)[g * 128 + cc];
    }
    __syncthreads();

    const int warp = tid >> 5;
    const int wg = (cta - 1) * 8 + warp;          // 0..1175
    const float bv = (lane < 4) ? bias[lane] : 0.f;
    const float4* in4 = reinterpret_cast<const float4*>(in);

    for (int ch = 0; ch < NCHUNK; ch++) {
        const int pe = (ch + 1) * CHUNK * B_DIM;
        for (int p = ch * CHUNK * B_DIM + wg; p < pe; p += NWARPW) {
            const float4* src = in4 + (long)p * 64;
            float4 a0 = src[lane];
            float4 a1 = src[lane + 32];
            float s[4];
#pragma unroll
            for (int g = 0; g < 4; g++) {
                float4 w = sW[g][lane];
                float t = a0.x * w.x + a0.y * w.y + a0.z * w.z + a0.w * w.w;
                w = sW[g][lane + 32];
                t += a1.x * w.x + a1.y * w.y + a1.z * w.z + a1.w * w.w;
                s[g] = t;
            }
            // packed 6-shuffle reduction of 4 sums
            bool b0 = lane & 1;
            float t01 = b0 ? s[0] : s[1];
            float k01 = b0 ? s[1] : s[0];
            k01 += __shfl_xor_sync(FULL, t01, 1);
            float t23 = b0 ? s[2] : s[3];
            float k23 = b0 ? s[3] : s[2];
            k23 += __shfl_xor_sync(FULL, t23, 1);
            bool b1 = lane & 2;
            float tv = b1 ? k01 : k23;
            float kv = b1 ? k23 : k01;
            kv += __shfl_xor_sync(FULL, tv, 2);
            kv += __shfl_xor_sync(FULL, kv, 4);
            kv += __shfl_xor_sync(FULL, kv, 8);
            kv += __shfl_xor_sync(FULL, kv, 16);
            if (lane < 4) g_xdot[p * 4 + lane] = kv + bv;
        }
        __threadfence();
        __syncthreads();
        if (tid == 0) atomicAdd(&g_xdone[ch], 1);
    }

    // ---- bcast phase: trail the recurrence ----
    float4* out4 = reinterpret_cast<float4*>(out);
    const int widx = (cta - 1) * 256 + tid;
    const long S4 = (long)T_DIM * B_DIM * H_DIM / 4;   // 8388608
    for (int ch = 0; ch < NCHUNK; ch++) {
        if (tid == 0) waitGe(&g_rdone, (ch + 1) * CHUNK);
        __syncthreads();
        const long base = (long)ch * CHUNK * (B_DIM * H_DIM / 4);
        const long end  = base + (long)CHUNK * (B_DIM * H_DIM / 4);
        for (long i = base + widx; i < end; i += NTHW) {
            int t = (int)(i >> 13);            // 8192 float4 per t
            int b = (int)(i >> 6) & 127;
            float v = g_h[t * B_DIM + b];      // warp-uniform load
            out4[i] = make_float4(v, v, v, v);
        }
    }
    // tails: hx (== h at t=1023) and cx
    for (long i = S4 + widx; i < S4 + 16384; i += NTHW) {
        int rr = (int)(i - S4);
        float v;
        if (rr < 8192) v = g_h[(T_DIM - 1) * B_DIM + (rr >> 6)];
        else           v = g_c[(rr - 8192) >> 6];
        out4[i] = make_float4(v, v, v, v);
    }
}

extern "C" void kernel_launch(void* const* d_in, const int* in_sizes, int n_in,
                              void* d_out, int out_size) {
    const float* in   = (const float*)d_in[0];   // [T,B,D]
    const float* Wt   = (const float*)d_in[1];   // [4, D+H]
    const float* bias = (const float*)d_in[2];   // [4]
    // d_in[3] (qw) mathematically has no effect on the output.
    float* out = (float*)d_out;

    k_zero<<<1, 32>>>();
    k_fused<<<NCTA, 256>>>(in, Wt, bias, out);
}

// round 9
// speedup vs baseline: 1.1142x; 1.0355x over previous
#include <cuda_runtime.h>

#define T_DIM 1024
#define B_DIM 128
#define H_DIM 256
#define CHUNK 64
#define NCHUNK 16                 // 16 * 64 = 1024 steps
#define NCTA 148
#define NWORK (NCTA - 1)          // 147 worker CTAs
#define NWARPW (NWORK * 8)        // worker warps (xdot)
#define NTHW (NWORK * 256)        // worker threads (bcast)

// Scratch (__device__ globals; allocation-free rule).
__device__ __align__(16) float g_xdot[(T_DIM + 8) * B_DIM * 4]; // [t][b][4], padded
__device__ __align__(16) float g_h[T_DIM * B_DIM];              // [t][b]
__device__ __align__(16) float g_c[B_DIM];
__device__ int g_xdone[NCHUNK];
__device__ int g_rdone;

// ---- fast math helpers -----------------------------------------------------
__device__ __forceinline__ float sin_ap(float x) {
    float r; asm("sin.approx.f32 %0, %1;" : "=f"(r) : "f"(x)); return r;
}
__device__ __forceinline__ float rcp_ap(float x) {
    float r; asm("rcp.approx.f32 %0, %1;" : "=f"(r) : "f"(x)); return r;
}

// sigmoid(s)-0.5 odd poly, |s|<=1, deg-7 (tail-corrected B3), abs err ~2.5e-6.
#define SB0 0.25f
#define SB1 (-2.0833333e-2f)
#define SB2 2.0833333e-3f
#define SB3 (-1.9162e-4f)

// tanh continued fraction depth 6, |x|<=2.2 (err ~3e-6; |c|<=2.07 provably). One rcp.
__device__ __forceinline__ float tanh_p6(float x) {
    float u  = x * x;
    float u2 = u * u;
    float n  = fmaf(fmaf(21.0f, u, 1260.0f), u, 10395.0f);
    float d  = fmaf(u2, u + 210.0f, fmaf(4725.0f, u, 10395.0f));
    return x * n * rcp_ap(d);
}

__device__ __forceinline__ void waitGe(const int* p, int v) {
    while (*(volatile const int*)p < v) __nanosleep(64);
}

// ---- zero the cross-CTA flags ----------------------------------------------
__global__ void k_zero() {
    int i = threadIdx.x;
    if (i < NCHUNK) g_xdone[i] = 0;
    if (i == NCHUNK) g_rdone = 0;
}

// ---- fused persistent kernel ----------------------------------------------
__global__ __launch_bounds__(256, 1) void k_fused(const float* __restrict__ in,
                                                  const float* __restrict__ Wt,
                                                  const float* __restrict__ bias,
                                                  float* __restrict__ out) {
    const int cta = blockIdx.x;
    const int tid = threadIdx.x;
    const int lane = tid & 31;
    const unsigned FULL = 0xffffffffu;

    if (cta == 0) {
        // ========== recurrence CTA: 4 warps, 1 chain per thread ==========
        if (tid >= 128) return;
        float wh[4];
#pragma unroll
        for (int g = 0; g < 4; g++) {
            const float* wr = Wt + g * 512 + 256;
            float s = 0.f;
#pragma unroll
            for (int k = 0; k < 8; k++) s += wr[lane + k * 32];
#pragma unroll
            for (int o = 16; o; o >>= 1) s += __shfl_xor_sync(FULL, s, o);
            wh[g] = s;
        }
        const float w0 = wh[0], w1 = wh[1], w2 = wh[2], w3 = wh[3];

        const int b = tid;
        const float4* xd4 = reinterpret_cast<const float4*>(g_xdot);

        if (tid == 0) waitGe(&g_xdone[0], NWORK);
        __syncthreads();

        float4 x0 = xd4[b];
        float lf = x0.x, li = x0.y, lg = x0.z, lo = x0.w;
        float4 buf[4];
#pragma unroll
        for (int k = 0; k < 4; k++) buf[k] = xd4[(k + 1) * B_DIM + b];

        float c = 0.f;
        for (int ch = 0; ch < NCHUNK; ch++) {
            int c2 = (ch + 1 < NCHUNK) ? ch + 1 : NCHUNK - 1;
            if (tid == 0) { waitGe(&g_xdone[ch], NWORK); waitGe(&g_xdone[c2], NWORK); }
            __syncthreads();

            const int t0 = ch * CHUNK;
#pragma unroll 4
            for (int t = t0; t < t0 + CHUNK; t++) {
                float4 nxt = buf[t & 3];
                buf[t & 3] = xd4[(t + 5) * B_DIM + b];   // prefetch, off-chain

                // stage 0: all four sins (MUFU, issued back-to-back)
                float sf = sin_ap(lf);
                float si = sin_ap(li);
                float sg = sin_ap(lg);
                float so = sin_ap(lo);

                // stage 1: all squares
                float uf = sf * sf;
                float ui = si * si;
                float ug = sg * sg;
                float uo = so * so;

                // stage 2..4: braided poly chains
                // sigmoids (f,i,o): deg-7 odd Horner (5 ops each)
                float pf = fmaf(SB3, uf, SB2);
                float pi = fmaf(SB3, ui, SB2);
                float po = fmaf(SB3, uo, SB2);
                // g: CF depth-4 tanh
                float ag = ug + 45.0f;
                float ng = fmaf(10.0f, ug, 105.0f);

                pf = fmaf(pf, uf, SB1);
                pi = fmaf(pi, ui, SB1);
                po = fmaf(po, uo, SB1);
                float dg = fmaf(ug, ag, 105.0f);
                float rg = rcp_ap(dg);

                pf = fmaf(pf, uf, SB0);
                pi = fmaf(pi, ui, SB0);
                po = fmaf(po, uo, SB0);
                float mg = sg * ng;

                float f  = fmaf(sf, pf, 0.5f);
                float i_ = fmaf(si, pi, 0.5f);
                float o  = fmaf(so, po, 0.5f);
                float gg = mg * rg;

                // cell + output
                c = fmaf(f, c, i_ * gg);
                float tc = tanh_p6(c);
                float h  = o * tc;
                lf = fmaf(w0, h, nxt.x);
                li = fmaf(w1, h, nxt.y);
                lg = fmaf(w2, h, nxt.z);
                lo = fmaf(w3, h, nxt.w);
                g_h[t * B_DIM + b] = h;                 // coalesced STG.32, off-chain
            }
            if (ch == NCHUNK - 1) g_c[b] = c;
            __threadfence();
            __syncthreads();
            if (tid == 0) *(volatile int*)&g_rdone = (ch + 1) * CHUNK;
        }
        return;
    }

    // ================= worker CTAs: xdot then bcast =================
    __shared__ float4 sW[4][64];
    for (int i = tid; i < 4 * 64; i += 256) {
        int g = i >> 6, cc = i & 63;
        sW[g][cc] = reinterpret_cast<const float4*>(Wt)[g * 128 + cc];
    }
    __syncthreads();

    const int warp = tid >> 5;
    const int wg = (cta - 1) * 8 + warp;          // 0..1175
    const float bv = (lane < 4) ? bias[lane] : 0.f;
    const float4* in4 = reinterpret_cast<const float4*>(in);

    for (int ch = 0; ch < NCHUNK; ch++) {
        const int pe = (ch + 1) * CHUNK * B_DIM;
        for (int p = ch * CHUNK * B_DIM + wg; p < pe; p += NWARPW) {
            const float4* src = in4 + (long)p * 64;
            float4 a0 = src[lane];
            float4 a1 = src[lane + 32];
            float s[4];
#pragma unroll
            for (int g = 0; g < 4; g++) {
                float4 w = sW[g][lane];
                float t = a0.x * w.x + a0.y * w.y + a0.z * w.z + a0.w * w.w;
                w = sW[g][lane + 32];
                t += a1.x * w.x + a1.y * w.y + a1.z * w.z + a1.w * w.w;
                s[g] = t;
            }
            // packed 6-shuffle reduction of 4 sums
            bool b0 = lane & 1;
            float t01 = b0 ? s[0] : s[1];
            float k01 = b0 ? s[1] : s[0];
            k01 += __shfl_xor_sync(FULL, t01, 1);
            float t23 = b0 ? s[2] : s[3];
            float k23 = b0 ? s[3] : s[2];
            k23 += __shfl_xor_sync(FULL, t23, 1);
            bool b1 = lane & 2;
            float tv = b1 ? k01 : k23;
            float kv = b1 ? k23 : k01;
            kv += __shfl_xor_sync(FULL, tv, 2);
            kv += __shfl_xor_sync(FULL, kv, 4);
            kv += __shfl_xor_sync(FULL, kv, 8);
            kv += __shfl_xor_sync(FULL, kv, 16);
            if (lane < 4) g_xdot[p * 4 + lane] = kv + bv;
        }
        __threadfence();
        __syncthreads();
        if (tid == 0) atomicAdd(&g_xdone[ch], 1);
    }

    // ---- bcast phase: trail the recurrence ----
    float4* out4 = reinterpret_cast<float4*>(out);
    const int widx = (cta - 1) * 256 + tid;
    const long S4 = (long)T_DIM * B_DIM * H_DIM / 4;   // 8388608
    for (int ch = 0; ch < NCHUNK; ch++) {
        if (tid == 0) waitGe(&g_rdone, (ch + 1) * CHUNK);
        __syncthreads();
        const long base = (long)ch * CHUNK * (B_DIM * H_DIM / 4);
        const long end  = base + (long)CHUNK * (B_DIM * H_DIM / 4);
        for (long i = base + widx; i < end; i += NTHW) {
            int t = (int)(i >> 13);            // 8192 float4 per t
            int b = (int)(i >> 6) & 127;
            float v = g_h[t * B_DIM + b];      // warp-uniform load
            out4[i] = make_float4(v, v, v, v);
        }
    }
    // tails: hx (== h at t=1023) and cx
    for (long i = S4 + widx; i < S4 + 16384; i += NTHW) {
        int rr = (int)(i - S4);
        float v;
        if (rr < 8192) v = g_h[(T_DIM - 1) * B_DIM + (rr >> 6)];
        else           v = g_c[(rr - 8192) >> 6];
        out4[i] = make_float4(v, v, v, v);
    }
}

extern "C" void kernel_launch(void* const* d_in, const int* in_sizes, int n_in,
                              void* d_out, int out_size) {
    const float* in   = (const float*)d_in[0];   // [T,B,D]
    const float* Wt   = (const float*)d_in[1];   // [4, D+H]
    const float* bias = (const float*)d_in[2];   // [4]
    // d_in[3] (qw) mathematically has no effect on the output.
    float* out = (float*)d_out;

    k_zero<<<1, 32>>>();
    k_fused<<<NCTA, 256>>>(in, Wt, bias, out);
}

// round 13
// speedup vs baseline: 1.3109x; 1.1765x over previous
#include <cuda_runtime.h>

#define T_DIM 1024
#define B_DIM 128
#define H_DIM 256
#define CHUNK 64
#define NCHUNK 16
#define NSEG 8
#define SEGLEN 128                // main steps per segment
#define NCTA 148
#define NREC NSEG                 // rec CTAs 0..7
#define NWORK (NCTA - NREC)       // 140 worker CTAs
#define NWARPW (NWORK * 8)
#define NTHW (NWORK * 256)

// Scratch (__device__ globals; allocation-free rule).
__device__ __align__(16) float g_xdot[(T_DIM + 8) * B_DIM * 4]; // [t][b][4], padded
__device__ __align__(16) float g_h[B_DIM * T_DIM];              // [b][t] (float4 stores)
__device__ __align__(16) float g_c[B_DIM];
__device__ int g_xdone[NCHUNK];
__device__ int g_sdone[NSEG];

// ---- fast math helpers (the proven R3 loop body) ---------------------------
__device__ __forceinline__ float sin_ap(float x) {
    float r; asm("sin.approx.f32 %0, %1;" : "=f"(r) : "f"(x)); return r;
}
__device__ __forceinline__ float rcp_ap(float x) {
    float r; asm("rcp.approx.f32 %0, %1;" : "=f"(r) : "f"(x)); return r;
}
__device__ __forceinline__ float sigm_poly(float s) {
    const float A0 = 0.25f, A1 = -2.0833333e-2f, A2 = 2.0833333e-3f,
                A3 = -2.1081349e-4f, A4 = 2.1356790e-5f, A5 = -2.1638685e-6f;
    float u  = s * s;
    float b0 = fmaf(A1, u, A0);
    float b1 = fmaf(A3, u, A2);
    float b2 = fmaf(A5, u, A4);
    float u2 = u * u;
    float u4 = u2 * u2;
    float p  = fmaf(b2, u4, fmaf(b1, u2, b0));
    return fmaf(s, p, 0.5f);
}
__device__ __forceinline__ float tanh_p5(float x) {
    float u = x * x;
    float n = fmaf(u + 105.0f, u, 945.0f);
    float d = fmaf(fmaf(15.0f, u, 420.0f), u, 945.0f);
    return x * n * rcp_ap(d);
}
__device__ __forceinline__ float tanh_p6(float x) {
    float u  = x * x;
    float u2 = u * u;
    float n  = fmaf(fmaf(21.0f, u, 1260.0f), u, 10395.0f);
    float d  = fmaf(u2, u + 210.0f, fmaf(4725.0f, u, 10395.0f));
    return x * n * rcp_ap(d);
}
__device__ __forceinline__ void waitGe(const int* p, int v) {
    while (*(volatile const int*)p < v) __nanosleep(64);
}

__global__ void k_zero() {
    int i = threadIdx.x;
    if (i < NCHUNK) g_xdone[i] = 0;
    else if (i < NCHUNK + NSEG) g_sdone[i - NCHUNK] = 0;
}

// ---- fused persistent kernel ----------------------------------------------
__global__ __launch_bounds__(256, 1) void k_fused(const float* __restrict__ in,
                                                  const float* __restrict__ Wt,
                                                  const float* __restrict__ bias,
                                                  float* __restrict__ out) {
    const int cta = blockIdx.x;
    const int tid = threadIdx.x;
    const int lane = tid & 31;
    const unsigned FULL = 0xffffffffu;

    if (cta < NREC) {
        // ====== recurrence segment CTA: 128 steps (+128 warmup for s>0) =====
        if (tid >= 128) return;
        float wh[4];
#pragma unroll
        for (int g = 0; g < 4; g++) {
            const float* wr = Wt + g * 512 + 256;
            float s = 0.f;
#pragma unroll
            for (int k = 0; k < 8; k++) s += wr[lane + k * 32];
#pragma unroll
            for (int o = 16; o; o >>= 1) s += __shfl_xor_sync(FULL, s, o);
            wh[g] = s;
        }
        const float w0 = wh[0], w1 = wh[1], w2 = wh[2], w3 = wh[3];

        const int b = tid;
        const int segStart = cta * SEGLEN;
        const int segEnd   = segStart + SEGLEN;
        const int tBegin   = cta ? segStart - SEGLEN : 0;   // warmup start
        const float4* xd4 = reinterpret_cast<const float4*>(g_xdot);
        float4* gh4 = reinterpret_cast<float4*>(g_h);

        if (tid == 0) {
            waitGe(&g_xdone[tBegin >> 6], NWORK);
            waitGe(&g_xdone[(tBegin >> 6) + 1], NWORK);
        }
        __syncthreads();

        float4 x0 = xd4[tBegin * B_DIM + b];
        float lf = x0.x, li = x0.y, lg = x0.z, lo = x0.w;
        float4 buf[4];
#pragma unroll
        for (int k = 0; k < 4; k++) buf[k] = xd4[(tBegin + k + 1) * B_DIM + b];

        float c = 0.f;
        float4 hv;
        for (int tc = tBegin; tc < segEnd; tc += CHUNK) {
            const int ch = tc >> 6;
            const int c2 = (tc + CHUNK < segEnd) ? ch + 1 : ch;
            if (tid == 0) { waitGe(&g_xdone[ch], NWORK); waitGe(&g_xdone[c2], NWORK); }
            __syncthreads();
            const bool wr = (tc >= segStart);
#pragma unroll 4
            for (int t = tc; t < tc + CHUNK; t++) {
                float4 nxt = buf[t & 3];
                buf[t & 3] = xd4[(t + 5) * B_DIM + b];   // off-chain prefetch

                float sf = sin_ap(lf);
                float si = sin_ap(li);
                float sg = sin_ap(lg);
                float so = sin_ap(lo);
                float f  = sigm_poly(sf);
                float i_ = sigm_poly(si);
                float gg = tanh_p5(sg);
                float o  = sigm_poly(so);
                c = fmaf(f, c, i_ * gg);
                float wo0 = w0 * o, wo1 = w1 * o, wo2 = w2 * o, wo3 = w3 * o;
                float tc_ = tanh_p6(c);
                lf = fmaf(wo0, tc_, nxt.x);
                li = fmaf(wo1, tc_, nxt.y);
                lg = fmaf(wo2, tc_, nxt.z);
                lo = fmaf(wo3, tc_, nxt.w);
                float h = o * tc_;
                int ph = t & 3;
                if (ph == 0) hv.x = h;
                else if (ph == 1) hv.y = h;
                else if (ph == 2) hv.z = h;
                else if (wr) { hv.w = h; gh4[(b * T_DIM + t - 3) >> 2] = hv; }
                else hv.w = h;
            }
        }
        if (cta == NREC - 1) g_c[b] = c;
        __threadfence();
        __syncthreads();
        if (tid == 0) *(volatile int*)&g_sdone[cta] = 1;
        return;
    }

    // ================= worker CTAs: xdot then bcast =================
    __shared__ float4 sW[4][64];
    for (int i = tid; i < 4 * 64; i += 256) {
        int g = i >> 6, cc = i & 63;
        sW[g][cc] = reinterpret_cast<const float4*>(Wt)[g * 128 + cc];
    }
    __syncthreads();

    const int warp = tid >> 5;
    const int wg = (cta - NREC) * 8 + warp;       // 0..1119
    const float bv = (lane < 4) ? bias[lane] : 0.f;
    const float4* in4 = reinterpret_cast<const float4*>(in);

    for (int ch = 0; ch < NCHUNK; ch++) {
        const int pe = (ch + 1) * CHUNK * B_DIM;
        for (int p = ch * CHUNK * B_DIM + wg; p < pe; p += NWARPW) {
            const float4* src = in4 + (long)p * 64;
            float4 a0 = src[lane];
            float4 a1 = src[lane + 32];
            float s[4];
#pragma unroll
            for (int g = 0; g < 4; g++) {
                float4 w = sW[g][lane];
                float t = a0.x * w.x + a0.y * w.y + a0.z * w.z + a0.w * w.w;
                w = sW[g][lane + 32];
                t += a1.x * w.x + a1.y * w.y + a1.z * w.z + a1.w * w.w;
                s[g] = t;
            }
            bool b0 = lane & 1;
            float t01 = b0 ? s[0] : s[1];
            float k01 = b0 ? s[1] : s[0];
            k01 += __shfl_xor_sync(FULL, t01, 1);
            float t23 = b0 ? s[2] : s[3];
            float k23 = b0 ? s[3] : s[2];
            k23 += __shfl_xor_sync(FULL, t23, 1);
            bool b1 = lane & 2;
            float tv = b1 ? k01 : k23;
            float kv = b1 ? k23 : k01;
            kv += __shfl_xor_sync(FULL, tv, 2);
            kv += __shfl_xor_sync(FULL, kv, 4);
            kv += __shfl_xor_sync(FULL, kv, 8);
            kv += __shfl_xor_sync(FULL, kv, 16);
            if (lane < 4) g_xdot[p * 4 + lane] = kv + bv;
        }
        __threadfence();
        __syncthreads();
        if (tid == 0) atomicAdd(&g_xdone[ch], 1);
    }

    // ---- bcast phase: trail segment completion ----
    float4* out4 = reinterpret_cast<float4*>(out);
    const int widx = (cta - NREC) * 256 + tid;
    const long S4 = (long)T_DIM * B_DIM * H_DIM / 4;   // 8388608
    const long SEG4 = (long)SEGLEN * B_DIM * H_DIM / 4;
    for (int s = 0; s < NSEG; s++) {
        if (tid == 0) waitGe(&g_sdone[s], 1);
        __syncthreads();
        const long base = (long)s * SEG4;
        const long end  = base + SEG4;
        for (long i = base + widx; i < end; i += NTHW) {
            int t = (int)(i >> 13);            // 8192 float4 per t
            int b = (int)(i >> 6) & 127;
            float v = g_h[b * T_DIM + t];      // warp-uniform load
            out4[i] = make_float4(v, v, v, v);
        }
    }
    // tails: hx (== h at t=1023) and cx
    for (long i = S4 + widx; i < S4 + 16384; i += NTHW) {
        int rr = (int)(i - S4);
        float v;
        if (rr < 8192) v = g_h[(rr >> 6) * T_DIM + (T_DIM - 1)];
        else           v = g_c[(rr - 8192) >> 6];
        out4[i] = make_float4(v, v, v, v);
    }
}

extern "C" void kernel_launch(void* const* d_in, const int* in_sizes, int n_in,
                              void* d_out, int out_size) {
    const float* in   = (const float*)d_in[0];   // [T,B,D]
    const float* Wt   = (const float*)d_in[1];   // [4, D+H]
    const float* bias = (const float*)d_in[2];   // [4]
    // d_in[3] (qw) mathematically has no effect on the output.
    float* out = (float*)d_out;

    k_zero<<<1, 32>>>();
    k_fused<<<NCTA, 256>>>(in, Wt, bias, out);
}

// round 15
// speedup vs baseline: 1.8313x; 1.3970x over previous
#include <cuda_runtime.h>

#define T_DIM 1024
#define B_DIM 128
#define H_DIM 256
#define CHUNK 64
#define NCHUNK 16
#define NSEG 16
#define SEGLEN 64                 // main steps per segment
#define WARM 128                  // warmup steps
#define NCTA 148
#define NREC NSEG                 // rec CTAs 0..15
#define NWORK (NCTA - NREC)       // 132 worker CTAs
#define BLK 512
#define NWARPW (NWORK * 16)       // 2112 worker warps
#define NTHW (NWORK * BLK)        // 67584 worker threads

// Scratch (__device__ globals; allocation-free rule).
__device__ __align__(16) float g_xdot[(T_DIM + 8) * B_DIM * 4]; // [t][b][4], padded
__device__ __align__(16) float g_h[B_DIM * T_DIM];              // [b][t] (float4 stores)
__device__ __align__(16) float g_c[B_DIM];
__device__ int g_xdone[NCHUNK];
__device__ int g_sdone[NSEG];

// ---- fast math helpers (the proven R3 loop body) ---------------------------
__device__ __forceinline__ float sin_ap(float x) {
    float r; asm("sin.approx.f32 %0, %1;" : "=f"(r) : "f"(x)); return r;
}
__device__ __forceinline__ float rcp_ap(float x) {
    float r; asm("rcp.approx.f32 %0, %1;" : "=f"(r) : "f"(x)); return r;
}
__device__ __forceinline__ float sigm_poly(float s) {
    const float A0 = 0.25f, A1 = -2.0833333e-2f, A2 = 2.0833333e-3f,
                A3 = -2.1081349e-4f, A4 = 2.1356790e-5f, A5 = -2.1638685e-6f;
    float u  = s * s;
    float b0 = fmaf(A1, u, A0);
    float b1 = fmaf(A3, u, A2);
    float b2 = fmaf(A5, u, A4);
    float u2 = u * u;
    float u4 = u2 * u2;
    float p  = fmaf(b2, u4, fmaf(b1, u2, b0));
    return fmaf(s, p, 0.5f);
}
__device__ __forceinline__ float tanh_p5(float x) {
    float u = x * x;
    float n = fmaf(u + 105.0f, u, 945.0f);
    float d = fmaf(fmaf(15.0f, u, 420.0f), u, 945.0f);
    return x * n * rcp_ap(d);
}
__device__ __forceinline__ float tanh_p6(float x) {
    float u  = x * x;
    float u2 = u * u;
    float n  = fmaf(fmaf(21.0f, u, 1260.0f), u, 10395.0f);
    float d  = fmaf(u2, u + 210.0f, fmaf(4725.0f, u, 10395.0f));
    return x * n * rcp_ap(d);
}
__device__ __forceinline__ void waitGe(const int* p, int v) {
    while (*(volatile const int*)p < v) __nanosleep(64);
}

__global__ void k_zero() {
    int i = threadIdx.x;
    if (i < NCHUNK) g_xdone[i] = 0;
    else if (i < NCHUNK + NSEG) g_sdone[i - NCHUNK] = 0;
}

// ---- fused persistent kernel ----------------------------------------------
__global__ __launch_bounds__(BLK, 1) void k_fused(const float* __restrict__ in,
                                                  const float* __restrict__ Wt,
                                                  const float* __restrict__ bias,
                                                  float* __restrict__ out) {
    const int cta = blockIdx.x;
    const int tid = threadIdx.x;
    const int lane = tid & 31;
    const unsigned FULL = 0xffffffffu;

    if (cta < NREC) {
        // ===== recurrence segment CTA: SEGLEN steps (+<=WARM warmup) =====
        if (tid >= 128) return;
        float wh[4];
#pragma unroll
        for (int g = 0; g < 4; g++) {
            const float* wr = Wt + g * 512 + 256;
            float s = 0.f;
#pragma unroll
            for (int k = 0; k < 8; k++) s += wr[lane + k * 32];
#pragma unroll
            for (int o = 16; o; o >>= 1) s += __shfl_xor_sync(FULL, s, o);
            wh[g] = s;
        }
        const float w0 = wh[0], w1 = wh[1], w2 = wh[2], w3 = wh[3];

        const int b = tid;
        const int segStart = cta * SEGLEN;
        const int segEnd   = segStart + SEGLEN;
        int tBegin = segStart - WARM; if (tBegin < 0) tBegin = 0;
        const float4* xd4 = reinterpret_cast<const float4*>(g_xdot);
        float4* gh4 = reinterpret_cast<float4*>(g_h);

        if (tid == 0) {
            waitGe(&g_xdone[tBegin >> 6], NWORK);
            waitGe(&g_xdone[(tBegin >> 6) + 1], NWORK);
        }
        __syncthreads();

        float4 x0 = xd4[tBegin * B_DIM + b];
        float lf = x0.x, li = x0.y, lg = x0.z, lo = x0.w;
        float4 buf[4];
#pragma unroll
        for (int k = 0; k < 4; k++) buf[k] = xd4[(tBegin + k + 1) * B_DIM + b];

        float c = 0.f;
        float4 hv;
        for (int tc = tBegin; tc < segEnd; tc += CHUNK) {
            const int ch = tc >> 6;
            const int c2 = (tc + CHUNK < segEnd) ? ch + 1 : ch;
            if (tid == 0) { waitGe(&g_xdone[ch], NWORK); waitGe(&g_xdone[c2], NWORK); }
            __syncthreads();
            const bool wr = (tc >= segStart);
#pragma unroll 4
            for (int t = tc; t < tc + CHUNK; t++) {
                float4 nxt = buf[t & 3];
                buf[t & 3] = xd4[(t + 5) * B_DIM + b];   // off-chain prefetch

                float sf = sin_ap(lf);
                float si = sin_ap(li);
                float sg = sin_ap(lg);
                float so = sin_ap(lo);
                float f  = sigm_poly(sf);
                float i_ = sigm_poly(si);
                float gg = tanh_p5(sg);
                float o  = sigm_poly(so);
                c = fmaf(f, c, i_ * gg);
                float wo0 = w0 * o, wo1 = w1 * o, wo2 = w2 * o, wo3 = w3 * o;
                float tc_ = tanh_p6(c);
                lf = fmaf(wo0, tc_, nxt.x);
                li = fmaf(wo1, tc_, nxt.y);
                lg = fmaf(wo2, tc_, nxt.z);
                lo = fmaf(wo3, tc_, nxt.w);
                float h = o * tc_;
                int ph = t & 3;
                if (ph == 0) hv.x = h;
                else if (ph == 1) hv.y = h;
                else if (ph == 2) hv.z = h;
                else if (wr) { hv.w = h; gh4[(b * T_DIM + t - 3) >> 2] = hv; }
                else hv.w = h;
            }
        }
        if (cta == NREC - 1) g_c[b] = c;
        __threadfence();
        __syncthreads();
        if (tid == 0) *(volatile int*)&g_sdone[cta] = 1;
        return;
    }

    // ================= worker CTAs: xdot then bcast =================
    __shared__ float4 sW[4][64];
    for (int i = tid; i < 4 * 64; i += BLK) {
        int g = i >> 6, cc = i & 63;
        sW[g][cc] = reinterpret_cast<const float4*>(Wt)[g * 128 + cc];
    }
    __syncthreads();

    const int warp = tid >> 5;
    const int wg = (cta - NREC) * 16 + warp;      // 0..2111
    const float bv = (lane < 4) ? bias[lane] : 0.f;
    const float4* in4 = reinterpret_cast<const float4*>(in);

    for (int ch = 0; ch < NCHUNK; ch++) {
        const int pe = (ch + 1) * CHUNK * B_DIM;
        int p = ch * CHUNK * B_DIM + wg;
        float4 a0, a1;
        if (p < pe) {                               // prime the pipeline
            a0 = in4[p * 64 + lane];
            a1 = in4[p * 64 + 32 + lane];
        }
        for (; p < pe; p += NWARPW) {
            int pn = p + NWARPW;
            float4 n0, n1;
            if (pn < pe) {                          // prefetch next pair (off-chain)
                n0 = in4[pn * 64 + lane];
                n1 = in4[pn * 64 + 32 + lane];
            }
            float s[4];
#pragma unroll
            for (int g = 0; g < 4; g++) {
                float4 w = sW[g][lane];
                float t = a0.x * w.x + a0.y * w.y + a0.z * w.z + a0.w * w.w;
                w = sW[g][lane + 32];
                t += a1.x * w.x + a1.y * w.y + a1.z * w.z + a1.w * w.w;
                s[g] = t;
            }
            // packed 6-shuffle reduction of 4 sums
            bool b0 = lane & 1;
            float t01 = b0 ? s[0] : s[1];
            float k01 = b0 ? s[1] : s[0];
            k01 += __shfl_xor_sync(FULL, t01, 1);
            float t23 = b0 ? s[2] : s[3];
            float k23 = b0 ? s[3] : s[2];
            k23 += __shfl_xor_sync(FULL, t23, 1);
            bool b1 = lane & 2;
            float tv = b1 ? k01 : k23;
            float kv = b1 ? k23 : k01;
            kv += __shfl_xor_sync(FULL, tv, 2);
            kv += __shfl_xor_sync(FULL, kv, 4);
            kv += __shfl_xor_sync(FULL, kv, 8);
            kv += __shfl_xor_sync(FULL, kv, 16);
            if (lane < 4) g_xdot[p * 4 + lane] = kv + bv;
            a0 = n0; a1 = n1;
        }
        __threadfence();
        __syncthreads();
        if (tid == 0) atomicAdd(&g_xdone[ch], 1);
    }

    // ---- bcast phase: trail segment completion ----
    float4* out4 = reinterpret_cast<float4*>(out);
    const int widx = (cta - NREC) * BLK + tid;
    const long S4 = (long)T_DIM * B_DIM * H_DIM / 4;   // 8388608
    const long SEG4 = (long)SEGLEN * B_DIM * H_DIM / 4;
    for (int s = 0; s < NSEG; s++) {
        if (tid == 0) waitGe(&g_sdone[s], 1);
        __syncthreads();
        const long base = (long)s * SEG4;
        const long end  = base + SEG4;
        for (long i = base + widx; i < end; i += NTHW) {
            int t = (int)(i >> 13);            // 8192 float4 per t
            int b = (int)(i >> 6) & 127;
            float v = g_h[b * T_DIM + t];      // warp-uniform load
            out4[i] = make_float4(v, v, v, v);
        }
    }
    // tails: hx (== h at t=1023) and cx
    for (long i = S4 + widx; i < S4 + 16384; i += NTHW) {
        int rr = (int)(i - S4);
        float v;
        if (rr < 8192) v = g_h[(rr >> 6) * T_DIM + (T_DIM - 1)];
        else           v = g_c[(rr - 8192) >> 6];
        out4[i] = make_float4(v, v, v, v);
    }
}

extern "C" void kernel_launch(void* const* d_in, const int* in_sizes, int n_in,
                              void* d_out, int out_size) {
    const float* in   = (const float*)d_in[0];   // [T,B,D]
    const float* Wt   = (const float*)d_in[1];   // [4, D+H]
    const float* bias = (const float*)d_in[2];   // [4]
    // d_in[3] (qw) mathematically has no effect on the output.
    float* out = (float*)d_out;

    k_zero<<<1, 32>>>();
    k_fused<<<NCTA, BLK>>>(in, Wt, bias, out);
}